// round 7
// baseline (speedup 1.0000x reference)
#include <cuda_runtime.h>
#include <cuda_fp16.h>
#include <cstdint>

#define NUSERS 100000
#define NJOBS  100000
#define NN     200000
#define EE     3200000
#define DD     64
#define BB     16384
#define NBLK_SCAN 196   // ceil(NN/1024)
#define GR 128          // GEMM rows per block

typedef unsigned long long ull;

// ---------------- scratch (static device globals; no allocation) ----------------
__device__ __half g_h16[(size_t)NN * DD];  // layer output (h1 = x@W1; later h2' = (x2@W2)*dinv)
__device__ __half g_a16[(size_t)NN * DD];  // relu(agg + b1), fp16
__device__ int    g_cnt[NN];
__device__ float  g_dinv[NN];
__device__ int    g_off[NN + 1];
__device__ int    g_cursor[NN];
__device__ int    g_csr[EE];
__device__ int    g_bsum[NBLK_SCAN];
__device__ int    g_is64_e, g_is64_u, g_is64_j;

// ---------------- f32x2 packed helpers ----------------
__device__ __forceinline__ ull packf2(float lo, float hi) {
    ull r; asm("mov.b64 %0, {%1, %2};" : "=l"(r) : "f"(lo), "f"(hi)); return r;
}
__device__ __forceinline__ void fma2(ull& d, ull a, ull b) {
    asm("fma.rn.f32x2 %0, %1, %2, %0;" : "+l"(d) : "l"(a), "l"(b));
}
__device__ __forceinline__ float2 unpackf2(ull v) {
    float2 r; asm("mov.b64 {%0, %1}, %2;" : "=f"(r.x), "=f"(r.y) : "l"(v)); return r;
}

// ---------------- detect (block 0) + zero counts ----------------
__global__ void k_detect_zero(const int* e32, const int* u32, const int* j32) {
    int i = blockIdx.x * blockDim.x + threadIdx.x;
    if (i < NN) g_cnt[i] = 0;
    if (blockIdx.x == 0) {
        __shared__ int any_e, any_u, any_j;
        if (threadIdx.x == 0) { any_e = any_u = any_j = 0; }
        __syncthreads();
        for (int k = threadIdx.x; k < 2048; k += blockDim.x) {
            if (e32[2 * k + 1]) atomicOr(&any_e, 1);
            if (u32[2 * k + 1]) atomicOr(&any_u, 1);
            if (j32[2 * k + 1]) atomicOr(&any_j, 1);
        }
        __syncthreads();
        if (threadIdx.x == 0) {
            g_is64_e = !any_e;
            g_is64_u = !any_u;
            g_is64_j = !any_j;
        }
    }
}

__device__ __forceinline__ int fetch_idx(const void* p, long long i, int is64) {
    return is64 ? (int)((const long long*)p)[i] : ((const int*)p)[i];
}

// ---------------- CSR build ----------------
__global__ void k_count(const void* edges) {
    int e = blockIdx.x * blockDim.x + threadIdx.x;
    int c = fetch_idx(edges, (long long)EE + e, g_is64_e);
    atomicAdd(&g_cnt[c], 1);
}

__global__ void k_scanA() {
    __shared__ int wsum[32];
    int t = threadIdx.x;
    int i = blockIdx.x * 1024 + t;
    int v = (i < NN) ? g_cnt[i] : 0;
    int x = v;
#pragma unroll
    for (int o = 1; o < 32; o <<= 1) {
        int y = __shfl_up_sync(0xFFFFFFFFu, x, o);
        if ((t & 31) >= o) x += y;
    }
    if ((t & 31) == 31) wsum[t >> 5] = x;
    __syncthreads();
    if (t < 32) {
        int s = wsum[t];
#pragma unroll
        for (int o = 1; o < 32; o <<= 1) {
            int y = __shfl_up_sync(0xFFFFFFFFu, s, o);
            if (t >= o) s += y;
        }
        wsum[t] = s;
    }
    __syncthreads();
    int pre = (t >= 32) ? wsum[(t >> 5) - 1] : 0;
    int incl = x + pre;
    if (i < NN) g_off[i] = incl - v;
    if (t == 1023) g_bsum[blockIdx.x] = incl;
}

// fused: per-block prefix over g_bsum + finalize offsets/cursors/dinv
__global__ void k_scanC() {
    __shared__ int pre_sh;
    int t = threadIdx.x;      // 1024
    int bid = blockIdx.x;     // 0..195
    if (t < 32) {
        int acc = 0;
        for (int k = t; k < bid; k += 32) acc += g_bsum[k];
#pragma unroll
        for (int o = 16; o > 0; o >>= 1) acc += __shfl_xor_sync(0xFFFFFFFFu, acc, o);
        if (t == 0) pre_sh = acc;
    }
    __syncthreads();
    int i = bid * 1024 + t;
    if (i < NN) {
        int o = g_off[i] + pre_sh;
        g_off[i] = o;
        g_cursor[i] = o;
        g_dinv[i] = rsqrtf((float)(g_cnt[i] + 1));
    }
    if (bid == NBLK_SCAN - 1 && t == 1023) g_off[NN] = EE;
}

__global__ void k_fill(const void* edges) {
    int e = blockIdx.x * blockDim.x + threadIdx.x;
    int is64 = g_is64_e;
    int r = fetch_idx(edges, e, is64);
    int c = fetch_idx(edges, (long long)EE + e, is64);
    int pos = atomicAdd(&g_cursor[c], 1);
    g_csr[pos] = r;
}

// ---------------- GEMM1: h16[node] = concat(userEmb,jobEmb)[node] @ W1 (NO dinv) ----------------
__global__ void k_gemm1(const float* __restrict__ srcA, const float* __restrict__ srcB,
                        const float* __restrict__ W, __half* __restrict__ out) {
    __shared__ float xs[GR][68];
    __shared__ float ws[64 * 64];

    int tid  = threadIdx.x;
    int row0 = blockIdx.x * GR;

    for (int idx = tid; idx < 1024; idx += 256)
        ((float4*)ws)[idx] = ((const float4*)W)[idx];

    for (int t = tid; t < GR * 16; t += 256) {
        int r = t >> 4, q = t & 15;
        int node = row0 + r;
        int ld = (node < NN) ? node : (NN - 1);
        const float* src = (ld < NUSERS) ? (srcA + (size_t)ld * DD)
                                         : (srcB + (size_t)(ld - NUSERS) * DD);
        *(float4*)&xs[r][q * 4] = ((const float4*)src)[q];
    }
    __syncthreads();

    int rg = tid >> 4;
    int cg = tid & 15;

    ull acc[8][2];
#pragma unroll
    for (int i = 0; i < 8; i++) { acc[i][0] = 0ULL; acc[i][1] = 0ULL; }

#pragma unroll 4
    for (int k4 = 0; k4 < 64; k4 += 4) {
        float4 xr[8];
#pragma unroll
        for (int i = 0; i < 8; i++)
            xr[i] = *(const float4*)&xs[rg * 8 + i][k4];
#pragma unroll
        for (int kk = 0; kk < 4; kk++) {
            ulonglong2 w2 = *(const ulonglong2*)&ws[(k4 + kk) * 64 + cg * 4];
#pragma unroll
            for (int i = 0; i < 8; i++) {
                float xv = (kk == 0) ? xr[i].x : (kk == 1) ? xr[i].y
                         : (kk == 2) ? xr[i].z : xr[i].w;
                ull xx = packf2(xv, xv);
                fma2(acc[i][0], xx, w2.x);
                fma2(acc[i][1], xx, w2.y);
            }
        }
    }

#pragma unroll
    for (int i = 0; i < 8; i++) {
        int node = row0 + rg * 8 + i;
        if (node >= NN) break;
        float2 p0 = unpackf2(acc[i][0]);
        float2 p1 = unpackf2(acc[i][1]);
        __half2 h0 = __floats2half2_rn(p0.x, p0.y);
        __half2 h1 = __floats2half2_rn(p1.x, p1.y);
        uint2 u;
        u.x = *(unsigned*)&h0;
        u.y = *(unsigned*)&h1;
        *(uint2*)(out + (size_t)node * DD + cg * 4) = u;
    }
}

// ---------------- GEMM2: h16[node] = (a16[node] @ W2) * dinv[node] ----------------
__global__ void k_gemm2(const __half* __restrict__ in, const float* __restrict__ W,
                        __half* __restrict__ out) {
    __shared__ float xs[GR][68];
    __shared__ float ws[64 * 64];

    int tid  = threadIdx.x;
    int row0 = blockIdx.x * GR;

    for (int idx = tid; idx < 1024; idx += 256)
        ((float4*)ws)[idx] = ((const float4*)W)[idx];

    const uint4* in4 = (const uint4*)in;   // 8 uint4 (64 halves) per row
    for (int t = tid; t < GR * 8; t += 256) {
        int r = t >> 3, q = t & 7;
        int node = row0 + r;
        int ld = (node < NN) ? node : (NN - 1);
        uint4 v = in4[(size_t)ld * 8 + q];
        float2 p0 = __half22float2(*(__half2*)&v.x);
        float2 p1 = __half22float2(*(__half2*)&v.y);
        float2 p2 = __half22float2(*(__half2*)&v.z);
        float2 p3 = __half22float2(*(__half2*)&v.w);
        float* dst = &xs[r][q * 8];
        dst[0] = p0.x; dst[1] = p0.y; dst[2] = p1.x; dst[3] = p1.y;
        dst[4] = p2.x; dst[5] = p2.y; dst[6] = p3.x; dst[7] = p3.y;
    }
    __syncthreads();

    int rg = tid >> 4;
    int cg = tid & 15;

    ull acc[8][2];
#pragma unroll
    for (int i = 0; i < 8; i++) { acc[i][0] = 0ULL; acc[i][1] = 0ULL; }

#pragma unroll 4
    for (int k4 = 0; k4 < 64; k4 += 4) {
        float4 xr[8];
#pragma unroll
        for (int i = 0; i < 8; i++)
            xr[i] = *(const float4*)&xs[rg * 8 + i][k4];
#pragma unroll
        for (int kk = 0; kk < 4; kk++) {
            ulonglong2 w2 = *(const ulonglong2*)&ws[(k4 + kk) * 64 + cg * 4];
#pragma unroll
            for (int i = 0; i < 8; i++) {
                float xv = (kk == 0) ? xr[i].x : (kk == 1) ? xr[i].y
                         : (kk == 2) ? xr[i].z : xr[i].w;
                ull xx = packf2(xv, xv);
                fma2(acc[i][0], xx, w2.x);
                fma2(acc[i][1], xx, w2.y);
            }
        }
    }

#pragma unroll
    for (int i = 0; i < 8; i++) {
        int node = row0 + rg * 8 + i;
        if (node >= NN) break;
        float s = g_dinv[node];
        float2 p0 = unpackf2(acc[i][0]);
        float2 p1 = unpackf2(acc[i][1]);
        __half2 h0 = __floats2half2_rn(p0.x * s, p0.y * s);
        __half2 h1 = __floats2half2_rn(p1.x * s, p1.y * s);
        uint2 u;
        u.x = *(unsigned*)&h0;
        u.y = *(unsigned*)&h1;
        *(uint2*)(out + (size_t)node * DD + cg * 4) = u;
    }
}

// ---------------- gather1: a16[n] = relu(dinv[n]*(dinv[n]*h[n] + sum dinv[s]*h[s]) + b1) ----------------
__device__ __forceinline__ void facc8h(float* f, uint4 v, float scale) {
    float2 p0 = __half22float2(*(__half2*)&v.x);
    float2 p1 = __half22float2(*(__half2*)&v.y);
    float2 p2 = __half22float2(*(__half2*)&v.z);
    float2 p3 = __half22float2(*(__half2*)&v.w);
    f[0] = fmaf(scale, p0.x, f[0]); f[1] = fmaf(scale, p0.y, f[1]);
    f[2] = fmaf(scale, p1.x, f[2]); f[3] = fmaf(scale, p1.y, f[3]);
    f[4] = fmaf(scale, p2.x, f[4]); f[5] = fmaf(scale, p2.y, f[5]);
    f[6] = fmaf(scale, p3.x, f[6]); f[7] = fmaf(scale, p3.y, f[7]);
}

__global__ void k_gather(const __half* __restrict__ hp, const float* __restrict__ b1,
                         __half* __restrict__ agg) {
    int n = (blockIdx.x * blockDim.x + threadIdx.x) >> 5;
    if (n >= NN) return;
    int lane = threadIdx.x & 31;
    int g = lane >> 3;
    int q = lane & 7;

    const uint4* h4 = (const uint4*)hp;
    int beg = g_off[n];
    int end = g_off[n + 1];

    float f[8] = {0, 0, 0, 0, 0, 0, 0, 0};

    int e = beg + g;
    while (e + 4 < end) {
        int s0 = g_csr[e];
        int s1 = g_csr[e + 4];
        float d0 = g_dinv[s0];
        float d1 = g_dinv[s1];
        uint4 v0 = h4[(size_t)s0 * 8 + q];
        uint4 v1 = h4[(size_t)s1 * 8 + q];
        facc8h(f, v0, d0);
        facc8h(f, v1, d1);
        e += 8;
    }
    if (e < end) {
        int s0 = g_csr[e];
        facc8h(f, h4[(size_t)s0 * 8 + q], g_dinv[s0]);
    }

#pragma unroll
    for (int i = 0; i < 8; i++) {
        f[i] += __shfl_xor_sync(0xFFFFFFFFu, f[i], 8);
        f[i] += __shfl_xor_sync(0xFFFFFFFFu, f[i], 16);
    }

    if (g == 0) {
        float dn = g_dinv[n];
        facc8h(f, h4[(size_t)n * 8 + q], dn);   // self term: dinv[n]*h[n]
        float4 bA = *(const float4*)(b1 + q * 8);
        float4 bB = *(const float4*)(b1 + q * 8 + 4);
        float r[8];
        r[0] = fmaxf(fmaf(f[0], dn, bA.x), 0.f);
        r[1] = fmaxf(fmaf(f[1], dn, bA.y), 0.f);
        r[2] = fmaxf(fmaf(f[2], dn, bA.z), 0.f);
        r[3] = fmaxf(fmaf(f[3], dn, bA.w), 0.f);
        r[4] = fmaxf(fmaf(f[4], dn, bB.x), 0.f);
        r[5] = fmaxf(fmaf(f[5], dn, bB.y), 0.f);
        r[6] = fmaxf(fmaf(f[6], dn, bB.z), 0.f);
        r[7] = fmaxf(fmaf(f[7], dn, bB.w), 0.f);
        __half2 h0 = __floats2half2_rn(r[0], r[1]);
        __half2 h1 = __floats2half2_rn(r[2], r[3]);
        __half2 h2 = __floats2half2_rn(r[4], r[5]);
        __half2 h3 = __floats2half2_rn(r[6], r[7]);
        uint4 u;
        u.x = *(unsigned*)&h0; u.y = *(unsigned*)&h1;
        u.z = *(unsigned*)&h2; u.w = *(unsigned*)&h3;
        ((uint4*)agg)[(size_t)n * 8 + q] = u;
    }
}

// ---------------- fused layer-2 gather + predictor (h2' includes dinv) ----------------
__device__ __forceinline__ void acc8h(float* f, uint4 v) {
    float2 p0 = __half22float2(*(__half2*)&v.x);
    float2 p1 = __half22float2(*(__half2*)&v.y);
    float2 p2 = __half22float2(*(__half2*)&v.z);
    float2 p3 = __half22float2(*(__half2*)&v.w);
    f[0] += p0.x; f[1] += p0.y; f[2] += p1.x; f[3] += p1.y;
    f[4] += p2.x; f[5] += p2.y; f[6] += p3.x; f[7] += p3.y;
}

__global__ void k_gpred(const void* uidx, const void* jidx,
                        const __half* __restrict__ hp,
                        const float* __restrict__ b2,
                        const float* __restrict__ pw,
                        const float* __restrict__ pb,
                        float* __restrict__ out) {
    int b = (blockIdx.x * blockDim.x + threadIdx.x) >> 5;
    if (b >= BB) return;
    int lane = threadIdx.x & 31;
    int side = lane >> 4;
    int sub  = (lane >> 3) & 1;
    int q    = lane & 7;

    int node;
    if (side == 0) node = fetch_idx(uidx, b, g_is64_u);
    else           node = NUSERS + fetch_idx(jidx, b, g_is64_j);

    const uint4* h4 = (const uint4*)hp;
    int beg = g_off[node];
    int end = g_off[node + 1];

    float f[8] = {0, 0, 0, 0, 0, 0, 0, 0};
    int e = beg + sub;
    while (e + 2 < end) {
        int s0 = g_csr[e];
        int s1 = g_csr[e + 2];
        uint4 v0 = h4[(size_t)s0 * 8 + q];
        uint4 v1 = h4[(size_t)s1 * 8 + q];
        acc8h(f, v0);
        acc8h(f, v1);
        e += 4;
    }
    if (e < end) {
        acc8h(f, h4[(size_t)g_csr[e] * 8 + q]);
    }

#pragma unroll
    for (int i = 0; i < 8; i++)
        f[i] += __shfl_xor_sync(0xFFFFFFFFu, f[i], 8);

    acc8h(f, h4[(size_t)node * 8 + q]);   // self
    float s = g_dinv[node];
    int d = q * 8;
    const float* pws = pw + side * DD + d;
    const float* b2s = b2 + d;
    float p = 0.f;
#pragma unroll
    for (int i = 0; i < 8; i++)
        p += (f[i] * s + b2s[i]) * pws[i];

    if (sub) p = 0.f;
#pragma unroll
    for (int o = 16; o > 0; o >>= 1)
        p += __shfl_xor_sync(0xFFFFFFFFu, p, o);

    if (lane == 0) out[b] = p + pb[0];
}

// ---------------- launch ----------------
extern "C" void kernel_launch(void* const* d_in, const int* in_sizes, int n_in,
                              void* d_out, int out_size) {
    const void*  edges    = d_in[0];
    const void*  uidx     = d_in[1];
    const void*  jidx     = d_in[2];
    const float* user_emb = (const float*)d_in[3];
    const float* job_emb  = (const float*)d_in[4];
    const float* W1 = (const float*)d_in[5];
    const float* b1 = (const float*)d_in[6];
    const float* W2 = (const float*)d_in[7];
    const float* b2 = (const float*)d_in[8];
    const float* pw = (const float*)d_in[9];
    const float* pb = (const float*)d_in[10];
    float* out = (float*)d_out;

    __half *gh, *ga;
    cudaGetSymbolAddress((void**)&gh, g_h16);
    cudaGetSymbolAddress((void**)&ga, g_a16);

    static cudaStream_t sB = nullptr;
    static cudaEvent_t evFork = nullptr, evJoin = nullptr;
    if (!sB) {
        cudaStreamCreateWithFlags(&sB, cudaStreamNonBlocking);
        cudaEventCreateWithFlags(&evFork, cudaEventDisableTiming);
        cudaEventCreateWithFlags(&evJoin, cudaEventDisableTiming);
    }

    // fork: GEMM1 (independent of the graph) runs concurrent with CSR build
    cudaEventRecord(evFork, 0);
    cudaStreamWaitEvent(sB, evFork, 0);
    k_gemm1<<<(NN + GR - 1) / GR, 256, 0, sB>>>(user_emb, job_emb, W1, gh);
    cudaEventRecord(evJoin, sB);

    // CSR build chain (default stream)
    k_detect_zero<<<(NN + 255) / 256, 256>>>((const int*)edges, (const int*)uidx, (const int*)jidx);
    k_count<<<EE / 256, 256>>>(edges);
    k_scanA<<<NBLK_SCAN, 1024>>>();
    k_scanC<<<NBLK_SCAN, 1024>>>();
    k_fill<<<EE / 256, 256>>>(edges);

    // join, then gather -> gemm2 -> predict
    cudaStreamWaitEvent(0, evJoin, 0);
    k_gather<<<(NN * 32 + 255) / 256, 256>>>(gh, b1, ga);
    k_gemm2<<<(NN + GR - 1) / GR, 256>>>(ga, W2, gh);
    k_gpred<<<(BB * 32 + 255) / 256, 256>>>(uidx, jidx, gh, b2, pw, pb, out);
}

// round 8
// speedup vs baseline: 1.3995x; 1.3995x over previous
#include <cuda_runtime.h>
#include <cuda_fp16.h>
#include <cstdint>

#define NUSERS 100000
#define NJOBS  100000
#define NN     200000
#define EE     3200000
#define DD     64
#define BB     16384
#define NBLK_SCAN 196   // ceil(NN/1024)
#define GR 128          // GEMM rows per block

typedef unsigned long long ull;

// ---------------- scratch (static device globals; no allocation) ----------------
__device__ __half g_h16[(size_t)NN * DD];  // h' = (x@W)*dinv[row] per layer, fp16
__device__ __half g_a16[(size_t)NN * DD];  // relu(agg + b1), fp16
__device__ int    g_cnt[NN];
__device__ float  g_dinv[NN];
__device__ int    g_off[NN + 1];
__device__ int    g_cursor[NN];
__device__ int    g_csr[EE];
__device__ int    g_bsum[NBLK_SCAN];
__device__ int    g_is64_e, g_is64_u, g_is64_j;

// ---------------- f32x2 packed helpers ----------------
__device__ __forceinline__ ull packf2(float lo, float hi) {
    ull r; asm("mov.b64 %0, {%1, %2};" : "=l"(r) : "f"(lo), "f"(hi)); return r;
}
__device__ __forceinline__ void fma2(ull& d, ull a, ull b) {
    asm("fma.rn.f32x2 %0, %1, %2, %0;" : "+l"(d) : "l"(a), "l"(b));
}
__device__ __forceinline__ float2 unpackf2(ull v) {
    float2 r; asm("mov.b64 {%0, %1}, %2;" : "=f"(r.x), "=f"(r.y) : "l"(v)); return r;
}

// ---------------- detect (block 0) + zero counts ----------------
__global__ void k_detect_zero(const int* e32, const int* u32, const int* j32) {
    int i = blockIdx.x * blockDim.x + threadIdx.x;
    if (i < NN) g_cnt[i] = 0;
    if (blockIdx.x == 0) {
        __shared__ int any_e, any_u, any_j;
        if (threadIdx.x == 0) { any_e = any_u = any_j = 0; }
        __syncthreads();
        for (int k = threadIdx.x; k < 2048; k += blockDim.x) {
            if (e32[2 * k + 1]) atomicOr(&any_e, 1);
            if (u32[2 * k + 1]) atomicOr(&any_u, 1);
            if (j32[2 * k + 1]) atomicOr(&any_j, 1);
        }
        __syncthreads();
        if (threadIdx.x == 0) {
            g_is64_e = !any_e;
            g_is64_u = !any_u;
            g_is64_j = !any_j;
        }
    }
}

__device__ __forceinline__ int fetch_idx(const void* p, long long i, int is64) {
    return is64 ? (int)((const long long*)p)[i] : ((const int*)p)[i];
}

// ---------------- CSR build ----------------
__global__ void k_count(const void* edges) {
    int e = blockIdx.x * blockDim.x + threadIdx.x;
    int c = fetch_idx(edges, (long long)EE + e, g_is64_e);
    atomicAdd(&g_cnt[c], 1);
}

__global__ void k_scanA() {
    __shared__ int wsum[32];
    int t = threadIdx.x;
    int i = blockIdx.x * 1024 + t;
    int v = (i < NN) ? g_cnt[i] : 0;
    int x = v;
#pragma unroll
    for (int o = 1; o < 32; o <<= 1) {
        int y = __shfl_up_sync(0xFFFFFFFFu, x, o);
        if ((t & 31) >= o) x += y;
    }
    if ((t & 31) == 31) wsum[t >> 5] = x;
    __syncthreads();
    if (t < 32) {
        int s = wsum[t];
#pragma unroll
        for (int o = 1; o < 32; o <<= 1) {
            int y = __shfl_up_sync(0xFFFFFFFFu, s, o);
            if (t >= o) s += y;
        }
        wsum[t] = s;
    }
    __syncthreads();
    int pre = (t >= 32) ? wsum[(t >> 5) - 1] : 0;
    int incl = x + pre;
    if (i < NN) g_off[i] = incl - v;
    if (t == 1023) g_bsum[blockIdx.x] = incl;
}

// fused: per-block prefix over g_bsum + finalize offsets/cursors/dinv
__global__ void k_scanC() {
    __shared__ int pre_sh;
    int t = threadIdx.x;      // 1024
    int bid = blockIdx.x;     // 0..195
    if (t < 32) {
        int acc = 0;
        for (int k = t; k < bid; k += 32) acc += g_bsum[k];
#pragma unroll
        for (int o = 16; o > 0; o >>= 1) acc += __shfl_xor_sync(0xFFFFFFFFu, acc, o);
        if (t == 0) pre_sh = acc;
    }
    __syncthreads();
    int i = bid * 1024 + t;
    if (i < NN) {
        int o = g_off[i] + pre_sh;
        g_off[i] = o;
        g_cursor[i] = o;
        g_dinv[i] = rsqrtf((float)(g_cnt[i] + 1));
    }
    if (bid == NBLK_SCAN - 1 && t == 1023) g_off[NN] = EE;
}

__global__ void k_fill(const void* edges) {
    int e = blockIdx.x * blockDim.x + threadIdx.x;
    int is64 = g_is64_e;
    int r = fetch_idx(edges, e, is64);
    int c = fetch_idx(edges, (long long)EE + e, is64);
    int pos = atomicAdd(&g_cursor[c], 1);
    g_csr[pos] = r;
}

// ---------------- GEMM1: h16[node] = (concat(userEmb,jobEmb)[node] @ W1) * dinv[node] ----------------
__global__ void k_gemm1(const float* __restrict__ srcA, const float* __restrict__ srcB,
                        const float* __restrict__ W, __half* __restrict__ out) {
    __shared__ float xs[GR][68];
    __shared__ float ws[64 * 64];

    int tid  = threadIdx.x;
    int row0 = blockIdx.x * GR;

    for (int idx = tid; idx < 1024; idx += 256)
        ((float4*)ws)[idx] = ((const float4*)W)[idx];

    for (int t = tid; t < GR * 16; t += 256) {
        int r = t >> 4, q = t & 15;
        int node = row0 + r;
        int ld = (node < NN) ? node : (NN - 1);
        const float* src = (ld < NUSERS) ? (srcA + (size_t)ld * DD)
                                         : (srcB + (size_t)(ld - NUSERS) * DD);
        *(float4*)&xs[r][q * 4] = ((const float4*)src)[q];
    }
    __syncthreads();

    int rg = tid >> 4;
    int cg = tid & 15;

    ull acc[8][2];
#pragma unroll
    for (int i = 0; i < 8; i++) { acc[i][0] = 0ULL; acc[i][1] = 0ULL; }

#pragma unroll 4
    for (int k4 = 0; k4 < 64; k4 += 4) {
        float4 xr[8];
#pragma unroll
        for (int i = 0; i < 8; i++)
            xr[i] = *(const float4*)&xs[rg * 8 + i][k4];
#pragma unroll
        for (int kk = 0; kk < 4; kk++) {
            ulonglong2 w2 = *(const ulonglong2*)&ws[(k4 + kk) * 64 + cg * 4];
#pragma unroll
            for (int i = 0; i < 8; i++) {
                float xv = (kk == 0) ? xr[i].x : (kk == 1) ? xr[i].y
                         : (kk == 2) ? xr[i].z : xr[i].w;
                ull xx = packf2(xv, xv);
                fma2(acc[i][0], xx, w2.x);
                fma2(acc[i][1], xx, w2.y);
            }
        }
    }

#pragma unroll
    for (int i = 0; i < 8; i++) {
        int node = row0 + rg * 8 + i;
        if (node >= NN) break;
        float s = g_dinv[node];
        float2 p0 = unpackf2(acc[i][0]);
        float2 p1 = unpackf2(acc[i][1]);
        __half2 h0 = __floats2half2_rn(p0.x * s, p0.y * s);
        __half2 h1 = __floats2half2_rn(p1.x * s, p1.y * s);
        uint2 u;
        u.x = *(unsigned*)&h0;
        u.y = *(unsigned*)&h1;
        *(uint2*)(out + (size_t)node * DD + cg * 4) = u;
    }
}

// ---------------- GEMM2: h16[node] = (a16[node] @ W2) * dinv[node], fp16 in/out ----------------
__global__ void k_gemm2(const __half* __restrict__ in, const float* __restrict__ W,
                        __half* __restrict__ out) {
    __shared__ float xs[GR][68];
    __shared__ float ws[64 * 64];

    int tid  = threadIdx.x;
    int row0 = blockIdx.x * GR;

    for (int idx = tid; idx < 1024; idx += 256)
        ((float4*)ws)[idx] = ((const float4*)W)[idx];

    const uint4* in4 = (const uint4*)in;   // 8 uint4 (64 halves) per row
    for (int t = tid; t < GR * 8; t += 256) {
        int r = t >> 3, q = t & 7;
        int node = row0 + r;
        int ld = (node < NN) ? node : (NN - 1);
        uint4 v = in4[(size_t)ld * 8 + q];
        float2 p0 = __half22float2(*(__half2*)&v.x);
        float2 p1 = __half22float2(*(__half2*)&v.y);
        float2 p2 = __half22float2(*(__half2*)&v.z);
        float2 p3 = __half22float2(*(__half2*)&v.w);
        float* dst = &xs[r][q * 8];
        dst[0] = p0.x; dst[1] = p0.y; dst[2] = p1.x; dst[3] = p1.y;
        dst[4] = p2.x; dst[5] = p2.y; dst[6] = p3.x; dst[7] = p3.y;
    }
    __syncthreads();

    int rg = tid >> 4;
    int cg = tid & 15;

    ull acc[8][2];
#pragma unroll
    for (int i = 0; i < 8; i++) { acc[i][0] = 0ULL; acc[i][1] = 0ULL; }

#pragma unroll 4
    for (int k4 = 0; k4 < 64; k4 += 4) {
        float4 xr[8];
#pragma unroll
        for (int i = 0; i < 8; i++)
            xr[i] = *(const float4*)&xs[rg * 8 + i][k4];
#pragma unroll
        for (int kk = 0; kk < 4; kk++) {
            ulonglong2 w2 = *(const ulonglong2*)&ws[(k4 + kk) * 64 + cg * 4];
#pragma unroll
            for (int i = 0; i < 8; i++) {
                float xv = (kk == 0) ? xr[i].x : (kk == 1) ? xr[i].y
                         : (kk == 2) ? xr[i].z : xr[i].w;
                ull xx = packf2(xv, xv);
                fma2(acc[i][0], xx, w2.x);
                fma2(acc[i][1], xx, w2.y);
            }
        }
    }

#pragma unroll
    for (int i = 0; i < 8; i++) {
        int node = row0 + rg * 8 + i;
        if (node >= NN) break;
        float s = g_dinv[node];
        float2 p0 = unpackf2(acc[i][0]);
        float2 p1 = unpackf2(acc[i][1]);
        __half2 h0 = __floats2half2_rn(p0.x * s, p0.y * s);
        __half2 h1 = __floats2half2_rn(p1.x * s, p1.y * s);
        uint2 u;
        u.x = *(unsigned*)&h0;
        u.y = *(unsigned*)&h1;
        *(uint2*)(out + (size_t)node * DD + cg * 4) = u;
    }
}

// ---------------- gather1: a16[n] = relu(dinv[n]*(h'[n] + sum h'[src]) + b1), fp16 out ----------------
__device__ __forceinline__ void acc8h(float* f, uint4 v) {
    float2 p0 = __half22float2(*(__half2*)&v.x);
    float2 p1 = __half22float2(*(__half2*)&v.y);
    float2 p2 = __half22float2(*(__half2*)&v.z);
    float2 p3 = __half22float2(*(__half2*)&v.w);
    f[0] += p0.x; f[1] += p0.y; f[2] += p1.x; f[3] += p1.y;
    f[4] += p2.x; f[5] += p2.y; f[6] += p3.x; f[7] += p3.y;
}

__global__ void k_gather(const __half* __restrict__ hp, const float* __restrict__ b1,
                         __half* __restrict__ agg) {
    int n = (blockIdx.x * blockDim.x + threadIdx.x) >> 5;
    if (n >= NN) return;
    int lane = threadIdx.x & 31;
    int g = lane >> 3;
    int q = lane & 7;

    const uint4* h4 = (const uint4*)hp;
    int beg = g_off[n];
    int end = g_off[n + 1];

    float f[8] = {0, 0, 0, 0, 0, 0, 0, 0};

    int e = beg + g;
    while (e + 4 < end) {
        int s0 = g_csr[e];
        int s1 = g_csr[e + 4];
        uint4 v0 = h4[(size_t)s0 * 8 + q];
        uint4 v1 = h4[(size_t)s1 * 8 + q];
        acc8h(f, v0);
        acc8h(f, v1);
        e += 8;
    }
    if (e < end) {
        acc8h(f, h4[(size_t)g_csr[e] * 8 + q]);
    }

#pragma unroll
    for (int i = 0; i < 8; i++) {
        f[i] += __shfl_xor_sync(0xFFFFFFFFu, f[i], 8);
        f[i] += __shfl_xor_sync(0xFFFFFFFFu, f[i], 16);
    }

    if (g == 0) {
        acc8h(f, h4[(size_t)n * 8 + q]);   // self term (h' already has dinv[n])
        float dn = g_dinv[n];
        float4 bA = *(const float4*)(b1 + q * 8);
        float4 bB = *(const float4*)(b1 + q * 8 + 4);
        float r[8];
        r[0] = fmaxf(fmaf(f[0], dn, bA.x), 0.f);
        r[1] = fmaxf(fmaf(f[1], dn, bA.y), 0.f);
        r[2] = fmaxf(fmaf(f[2], dn, bA.z), 0.f);
        r[3] = fmaxf(fmaf(f[3], dn, bA.w), 0.f);
        r[4] = fmaxf(fmaf(f[4], dn, bB.x), 0.f);
        r[5] = fmaxf(fmaf(f[5], dn, bB.y), 0.f);
        r[6] = fmaxf(fmaf(f[6], dn, bB.z), 0.f);
        r[7] = fmaxf(fmaf(f[7], dn, bB.w), 0.f);
        __half2 h0 = __floats2half2_rn(r[0], r[1]);
        __half2 h1 = __floats2half2_rn(r[2], r[3]);
        __half2 h2 = __floats2half2_rn(r[4], r[5]);
        __half2 h3 = __floats2half2_rn(r[6], r[7]);
        uint4 u;
        u.x = *(unsigned*)&h0; u.y = *(unsigned*)&h1;
        u.z = *(unsigned*)&h2; u.w = *(unsigned*)&h3;
        ((uint4*)agg)[(size_t)n * 8 + q] = u;
    }
}

// ---------------- fused layer-2 gather + predictor (h2' includes dinv[src]) ----------------
__global__ void k_gpred(const void* uidx, const void* jidx,
                        const __half* __restrict__ hp,
                        const float* __restrict__ b2,
                        const float* __restrict__ pw,
                        const float* __restrict__ pb,
                        float* __restrict__ out) {
    int b = (blockIdx.x * blockDim.x + threadIdx.x) >> 5;
    if (b >= BB) return;
    int lane = threadIdx.x & 31;
    int side = lane >> 4;
    int sub  = (lane >> 3) & 1;
    int q    = lane & 7;

    int node;
    if (side == 0) node = fetch_idx(uidx, b, g_is64_u);
    else           node = NUSERS + fetch_idx(jidx, b, g_is64_j);

    const uint4* h4 = (const uint4*)hp;
    int beg = g_off[node];
    int end = g_off[node + 1];

    float f[8] = {0, 0, 0, 0, 0, 0, 0, 0};
    int e = beg + sub;
    while (e + 2 < end) {
        int s0 = g_csr[e];
        int s1 = g_csr[e + 2];
        uint4 v0 = h4[(size_t)s0 * 8 + q];
        uint4 v1 = h4[(size_t)s1 * 8 + q];
        acc8h(f, v0);
        acc8h(f, v1);
        e += 4;
    }
    if (e < end) {
        acc8h(f, h4[(size_t)g_csr[e] * 8 + q]);
    }

#pragma unroll
    for (int i = 0; i < 8; i++)
        f[i] += __shfl_xor_sync(0xFFFFFFFFu, f[i], 8);

    acc8h(f, h4[(size_t)node * 8 + q]);   // self
    float s = g_dinv[node];
    int d = q * 8;
    const float* pws = pw + side * DD + d;
    const float* b2s = b2 + d;
    float p = 0.f;
#pragma unroll
    for (int i = 0; i < 8; i++)
        p += (f[i] * s + b2s[i]) * pws[i];

    if (sub) p = 0.f;
#pragma unroll
    for (int o = 16; o > 0; o >>= 1)
        p += __shfl_xor_sync(0xFFFFFFFFu, p, o);

    if (lane == 0) out[b] = p + pb[0];
}

// ---------------- launch ----------------
extern "C" void kernel_launch(void* const* d_in, const int* in_sizes, int n_in,
                              void* d_out, int out_size) {
    const void*  edges    = d_in[0];
    const void*  uidx     = d_in[1];
    const void*  jidx     = d_in[2];
    const float* user_emb = (const float*)d_in[3];
    const float* job_emb  = (const float*)d_in[4];
    const float* W1 = (const float*)d_in[5];
    const float* b1 = (const float*)d_in[6];
    const float* W2 = (const float*)d_in[7];
    const float* b2 = (const float*)d_in[8];
    const float* pw = (const float*)d_in[9];
    const float* pb = (const float*)d_in[10];
    float* out = (float*)d_out;

    __half *gh, *ga;
    cudaGetSymbolAddress((void**)&gh, g_h16);
    cudaGetSymbolAddress((void**)&ga, g_a16);

    // CSR build (single stream; chip is saturated here — no overlap wins)
    k_detect_zero<<<(NN + 255) / 256, 256>>>((const int*)edges, (const int*)uidx, (const int*)jidx);
    k_count<<<EE / 256, 256>>>(edges);
    k_scanA<<<NBLK_SCAN, 1024>>>();
    k_scanC<<<NBLK_SCAN, 1024>>>();
    k_fill<<<EE / 256, 256>>>(edges);

    // ---- layer 1 ----
    k_gemm1<<<(NN + GR - 1) / GR, 256>>>(user_emb, job_emb, W1, gh);
    k_gather<<<(NN * 32 + 255) / 256, 256>>>(gh, b1, ga);

    // ---- layer 2 (aggregation fused into predictor at sampled nodes) ----
    k_gemm2<<<(NN + GR - 1) / GR, 256>>>(ga, W2, gh);
    k_gpred<<<(BB * 32 + 255) / 256, 256>>>(uidx, jidx, gh, b2, pw, pb, out);
}